// round 4
// baseline (speedup 1.0000x reference)
#include <cuda_runtime.h>

// Problem constants
#define C 512
#define L 16384
#define NB 16

// ---------------- device scratch (no allocations allowed) ----------------
// Augmented matrix [ I+A | I-A ] -> after blocked Gauss-Jordan the right
// half holds K = (I+A)^{-1}(I-A).
__device__ float g_AUG[C * 2 * C];      // 512 x 1024, row stride 1024 (2 MB)
__device__ float g_Pinv[64 * 64];       // inverse of current 64x64 pivot block
__device__ float g_G[C * 64];           // row-transform matrix (W - I_cols)
__device__ float g_R[64 * 2 * C];       // saved old pivot-block rows (64 x 1024)

// ---------------- 1) build augmented matrix ----------------
__global__ void setup_aug(const float* __restrict__ w) {
    int r = blockIdx.x;
    for (int c = threadIdx.x; c < C; c += blockDim.x) {
        float a = w[r * C + c] - w[c * C + r];          // A = W - W^T
        float d = (r == c) ? 1.0f : 0.0f;
        g_AUG[r * 1024 + c]       = d + a;              // I + A
        g_AUG[r * 1024 + C + c]   = d - a;              // I - A
    }
}

// ---------------- 2) invert 64x64 pivot block (1 CTA, partial pivoting) ----
__global__ void invert_block(int p) {
    __shared__ float Ms[64][66];
    __shared__ float Is[64][66];
    __shared__ int   s_piv;
    int t = threadIdx.x;  // 256 threads

    for (int idx = t; idx < 64 * 64; idx += 256) {
        int r = idx >> 6, c = idx & 63;
        Ms[r][c] = g_AUG[(p + r) * 1024 + p + c];
        Is[r][c] = (r == c) ? 1.0f : 0.0f;
    }
    __syncthreads();

    int rr = t >> 2;          // row this thread updates (0..63)
    int gg = t & 3;           // column quarter (16 cols each)

    for (int k = 0; k < 64; ++k) {
        // --- pivot search (warp 0) ---
        if (t < 32) {
            float best = -1.0f; int bi = k;
            for (int r = k + t; r < 64; r += 32) {
                float v = fabsf(Ms[r][k]);
                if (v > best) { best = v; bi = r; }
            }
            #pragma unroll
            for (int off = 16; off; off >>= 1) {
                float ob = __shfl_down_sync(0xffffffffu, best, off);
                int   oi = __shfl_down_sync(0xffffffffu, bi,   off);
                if (ob > best) { best = ob; bi = oi; }
            }
            if (t == 0) s_piv = bi;
        }
        __syncthreads();
        int pv = s_piv;
        // --- swap rows k <-> pv ---
        if (pv != k) {
            for (int c = t; c < 64; c += 256) {
                float tmp = Ms[k][c]; Ms[k][c] = Ms[pv][c]; Ms[pv][c] = tmp;
                tmp = Is[k][c]; Is[k][c] = Is[pv][c]; Is[pv][c] = tmp;
            }
        }
        __syncthreads();
        // --- scale row k ---
        float inv = 1.0f / Ms[k][k];
        __syncthreads();
        for (int c = t; c < 64; c += 256) { Ms[k][c] *= inv; Is[k][c] *= inv; }
        __syncthreads();
        // --- eliminate ---
        float m = Ms[rr][k];
        __syncthreads();
        if (rr != k) {
            #pragma unroll
            for (int cc = 0; cc < 16; ++cc) {
                int c = gg * 16 + cc;
                Ms[rr][c] -= m * Ms[k][c];
                Is[rr][c] -= m * Is[k][c];
            }
        }
        __syncthreads();
    }

    for (int idx = t; idx < 64 * 64; idx += 256) {
        int r = idx >> 6, c = idx & 63;
        g_Pinv[idx] = Is[r][c];
    }
}

// ---------------- 3) build G = W - I_cols, save old pivot rows R ----------
// W[blockrows] = P11^{-1}; W[other r] = -P21[r]·P11^{-1}
__global__ void compute_G(int p) {
    int cta = blockIdx.x;
    if (cta == 8) {  // copy R = old pivot-block rows (full width)
        for (int idx = threadIdx.x; idx < 64 * 1024; idx += blockDim.x)
            g_R[idx] = g_AUG[(p + (idx >> 10)) * 1024 + (idx & 1023)];
        return;
    }
    __shared__ float Ps[64][65];
    for (int idx = threadIdx.x; idx < 64 * 64; idx += 256)
        Ps[idx >> 6][idx & 63] = g_Pinv[idx];
    __syncthreads();

    int r0 = cta * 64;
    int blockgroup = p >> 6;
    if (cta == blockgroup) {
        for (int idx = threadIdx.x; idx < 64 * 64; idx += 256) {
            int r = idx >> 6, k = idx & 63;
            g_G[(r0 + r) * 64 + k] = Ps[r][k] - ((r == k) ? 1.0f : 0.0f);
        }
    } else {
        int t = threadIdx.x;
        int r = t >> 2, q = t & 3;           // row, 16-wide k quarter
        float acc[16];
        #pragma unroll
        for (int i = 0; i < 16; ++i) acc[i] = 0.0f;
        const float* arow = &g_AUG[(r0 + r) * 1024 + p];
        for (int j = 0; j < 64; ++j) {
            float a = arow[j];
            #pragma unroll
            for (int i = 0; i < 16; ++i) acc[i] += a * Ps[j][q * 16 + i];
        }
        #pragma unroll
        for (int i = 0; i < 16; ++i)
            g_G[(r0 + r) * 64 + q * 16 + i] = -acc[i];
    }
}

// ---------------- 4) trailing update AUG[:, c>=p+64] += G · R ------------
__global__ void trailing_update(int p) {
    int c0 = p + 64 + blockIdx.x * 64;
    int r0 = blockIdx.y * 64;
    __shared__ float Gs[64][65];
    __shared__ float Rs[64][65];
    int t = threadIdx.x;
    for (int idx = t; idx < 64 * 64; idx += 256) {
        int r = idx >> 6, c = idx & 63;
        Gs[r][c] = g_G[(r0 + r) * 64 + c];
        Rs[r][c] = g_R[r * 1024 + c0 + c];
    }
    __syncthreads();
    int tx = t & 15, ty = t >> 4;
    float acc[4][4] = {};
    for (int k = 0; k < 64; ++k) {
        float a[4], b[4];
        #pragma unroll
        for (int i = 0; i < 4; ++i) a[i] = Gs[ty * 4 + i][k];
        #pragma unroll
        for (int j = 0; j < 4; ++j) b[j] = Rs[k][tx * 4 + j];
        #pragma unroll
        for (int i = 0; i < 4; ++i)
            #pragma unroll
            for (int j = 0; j < 4; ++j) acc[i][j] += a[i] * b[j];
    }
    #pragma unroll
    for (int i = 0; i < 4; ++i)
        #pragma unroll
        for (int j = 0; j < 4; ++j) {
            int r = r0 + ty * 4 + i, c = c0 + tx * 4 + j;
            g_AUG[r * 1024 + c] += acc[i][j];
        }
}

// ---------------- 5) main GEMM: y[b,j,n] = sum_i K[j,i] x[b,i,n] ----------
// K lives at g_AUG[j*1024 + 512 + i]. Classic 128x128x8 double-buffered
// SGEMM, 256 threads, 8x8 per thread.
__global__ __launch_bounds__(256, 2)
void mix_gemm(const float* __restrict__ X, float* __restrict__ Y) {
    const int n0 = blockIdx.x * 128;
    const int j0 = blockIdx.y * 128;
    const long long boff = (long long)blockIdx.z * C * L;
    const float* Xb = X + boff;
    float*       Yb = Y + boff;

    __shared__ float As[2][8][128];
    __shared__ float Bs[2][8][128];

    int t  = threadIdx.x;
    int tx = t & 15, ty = t >> 4;

    // global-load mappings
    int arow = t >> 1, ac4 = (t & 1) * 4;        // A tile: 128 rows x 8 cols
    int brow = t >> 5, bcol = (t & 31) * 4;      // B tile: 8 rows x 128 cols

    float4 aReg = *(const float4*)&g_AUG[(j0 + arow) * 1024 + 512 + ac4];
    float4 bReg = *(const float4*)&Xb[(long long)brow * L + n0 + bcol];

    As[0][ac4 + 0][arow] = aReg.x;
    As[0][ac4 + 1][arow] = aReg.y;
    As[0][ac4 + 2][arow] = aReg.z;
    As[0][ac4 + 3][arow] = aReg.w;
    *(float4*)&Bs[0][brow][bcol] = bReg;
    __syncthreads();

    float acc[8][8] = {};
    int buf = 0;
    for (int k0 = 0; k0 < C; k0 += 8) {
        if (k0 + 8 < C) {
            aReg = *(const float4*)&g_AUG[(j0 + arow) * 1024 + 512 + k0 + 8 + ac4];
            bReg = *(const float4*)&Xb[(long long)(k0 + 8 + brow) * L + n0 + bcol];
        }
        #pragma unroll
        for (int kk = 0; kk < 8; ++kk) {
            float a[8], b[8];
            *(float4*)&a[0] = *(const float4*)&As[buf][kk][ty * 8];
            *(float4*)&a[4] = *(const float4*)&As[buf][kk][ty * 8 + 4];
            *(float4*)&b[0] = *(const float4*)&Bs[buf][kk][tx * 4];
            *(float4*)&b[4] = *(const float4*)&Bs[buf][kk][64 + tx * 4];
            #pragma unroll
            for (int i = 0; i < 8; ++i)
                #pragma unroll
                for (int j = 0; j < 8; ++j)
                    acc[i][j] += a[i] * b[j];
        }
        if (k0 + 8 < C) {
            buf ^= 1;
            As[buf][ac4 + 0][arow] = aReg.x;
            As[buf][ac4 + 1][arow] = aReg.y;
            As[buf][ac4 + 2][arow] = aReg.z;
            As[buf][ac4 + 3][arow] = aReg.w;
            *(float4*)&Bs[buf][brow][bcol] = bReg;
            __syncthreads();
        }
    }

    #pragma unroll
    for (int i = 0; i < 8; ++i) {
        float4 v0 = make_float4(acc[i][0], acc[i][1], acc[i][2], acc[i][3]);
        float4 v1 = make_float4(acc[i][4], acc[i][5], acc[i][6], acc[i][7]);
        float* yr = &Yb[(long long)(j0 + ty * 8 + i) * L];
        *(float4*)&yr[n0 + tx * 4]      = v0;
        *(float4*)&yr[n0 + 64 + tx * 4] = v1;
    }
}

// ---------------- launch ----------------
extern "C" void kernel_launch(void* const* d_in, const int* in_sizes, int n_in,
                              void* d_out, int out_size) {
    const float* x = (const float*)d_in[0];
    const float* w = (const float*)d_in[1];
    // defensive: identify operands by size (x is 16*512*16384, w is 512*512)
    if (n_in >= 2 && in_sizes[0] == C * C) {
        const float* tmp = x; x = w; w = tmp;
    }

    setup_aug<<<C, 256>>>(w);

    for (int b = 0; b < 8; ++b) {
        int p = b * 64;
        invert_block<<<1, 256>>>(p);
        compute_G<<<9, 256>>>(p);
        int trailing = 1024 - (p + 64);
        dim3 g3(trailing / 64, 8);
        trailing_update<<<g3, 256>>>(p);
    }

    dim3 gg(L / 128, C / 128, NB);
    mix_gemm<<<gg, 256>>>(x, (float*)d_out);
}